// round 10
// baseline (speedup 1.0000x reference)
#include <cuda_runtime.h>
#include <cstdint>

#define NSEG   10000
#define NROWS  500000
#define D      128
#define BM     72
#define BLK    576
#define NWARP  (BLK / 32)                 // 18
#define NBLK   ((NSEG + BM - 1) / BM)     // 139
#define XS_STRIDE 132
#define SMEM_T ((D * D + BM * XS_STRIDE) * 4)   // 103552 bytes

// graph may be int32 or int64 depending on jax x64 config.
// int32 layout: word[2*NSEG-1] = ends[NSEG-1] = N-1 (nonzero).
// int64 layout: word[2*NSEG-1] = high half of element NSEG-1 -> 0.
__device__ __forceinline__ bool graph_is64(const int* __restrict__ g) {
    return g[2 * NSEG - 1] == 0;
}
__device__ __forceinline__ int seg_start(const int* __restrict__ g, bool is64, int s) {
    return is64 ? g[4 * s] : g[2 * s];
}
__device__ __forceinline__ int seg_end(const int* __restrict__ g, bool is64, int s) {
    return is64 ? g[4 * s + 2] : g[2 * s + 1];
}

__device__ __forceinline__ float4 ldcs4(const float4* p) {
    float4 v;
    asm volatile("ld.global.cs.v4.f32 {%0,%1,%2,%3}, [%4];"
                 : "=f"(v.x), "=f"(v.y), "=f"(v.z), "=f"(v.w) : "l"(p));
    return v;
}

// ---------------------------------------------------------------------------
// FUSED kernel: one block per gemm tile (72 segments). Phases:
//  0. stage W transposed into smem ws (scattered float4 reads, conflict-free
//     STS since n is the fast axis); zero xs; load seg table into smem.
//  1. streaming sum: block's contiguous row range split into 18 equal
//     per-warp chunks; unroll-8 LDG.128 (.cs) per warp; per-segment register
//     accumulators flushed into xs: STS.128 if segment wholly inside chunk,
//     smem atomicAdd for chunk-boundary segments.
//  2. one __syncthreads, then register-blocked gemm from ws/xs (R7 body),
//     epilogue adds count*b, writes out.
// ---------------------------------------------------------------------------
__global__ void __launch_bounds__(BLK) fused_kernel(
    const float* __restrict__ input,
    const int*   __restrict__ graph,
    const float* __restrict__ W,
    const float* __restrict__ b,
    float*       __restrict__ out)
{
    extern __shared__ float sm[];
    float* ws = sm;            // ws[k*D + n]  (transposed W, 64KB)
    float* xs = sm + D * D;    // xs[m*XS_STRIDE + k] (segment sums)

    __shared__ int sst[BM];
    __shared__ int sen[BM];

    const int tid = threadIdx.x;
    const int m0  = blockIdx.x * BM;
    const int ns  = min(m0 + BM, NSEG) - m0;

    // --- Phase 0: stage + zero + tables -----------------------------------
    // Transpose W: thread reads W[n][4j..4j+3] (float4), writes 4 scalars
    // ws[(4j+jj)*D + n]. n is fast within the warp -> STS conflict-free.
    for (int lin = tid; lin < D * D / 4; lin += BLK) {
        int j = lin >> 7;          // 0..31
        int n = lin & 127;
        float4 w = ((const float4*)W)[n * 32 + j];
        ws[(4 * j + 0) * D + n] = w.x;
        ws[(4 * j + 1) * D + n] = w.y;
        ws[(4 * j + 2) * D + n] = w.z;
        ws[(4 * j + 3) * D + n] = w.w;
    }
    // Zero xs (accumulator target).
    for (int lin = tid; lin < BM * XS_STRIDE / 4; lin += BLK)
        ((float4*)xs)[lin] = make_float4(0.f, 0.f, 0.f, 0.f);
    // Segment table.
    {
        const bool is64 = graph_is64(graph);
        for (int i = tid; i < ns; i += BLK) {
            sst[i] = seg_start(graph, is64, m0 + i);
            sen[i] = seg_end(graph, is64, m0 + i);
        }
    }
    __syncthreads();

    // --- Phase 1: streaming segment sums ----------------------------------
    const int R0 = sst[0];
    const int R1 = sen[ns - 1] + 1;           // exclusive
    const int ck = (R1 - R0 + NWARP - 1) / NWARP;

    const int warp = tid >> 5;
    const int lane = tid & 31;
    const int a    = R0 + warp * ck;
    const int bnd  = min(a + ck, R1);

    if (a < bnd) {
        // Binary search: segment containing row a.
        int lo = 0, hi = ns - 1;
        while (lo < hi) {
            int mid = (lo + hi + 1) >> 1;
            if (sst[mid] <= a) lo = mid; else hi = mid - 1;
        }
        int seg = lo;

        int r = a;
        while (r < bnd) {
            const int e   = min(sen[seg] + 1, bnd);
            const int len = e - r;

            const float4* p = (const float4*)input + (long long)r * 32 + lane;
            float4 acc = make_float4(0.f, 0.f, 0.f, 0.f);

            int i = 0;
            for (; i + 8 <= len; i += 8) {
                float4 v0 = ldcs4(p + 0 * 32), v1 = ldcs4(p + 1 * 32);
                float4 v2 = ldcs4(p + 2 * 32), v3 = ldcs4(p + 3 * 32);
                float4 v4 = ldcs4(p + 4 * 32), v5 = ldcs4(p + 5 * 32);
                float4 v6 = ldcs4(p + 6 * 32), v7 = ldcs4(p + 7 * 32);
                acc.x += ((v0.x + v1.x) + (v2.x + v3.x)) + ((v4.x + v5.x) + (v6.x + v7.x));
                acc.y += ((v0.y + v1.y) + (v2.y + v3.y)) + ((v4.y + v5.y) + (v6.y + v7.y));
                acc.z += ((v0.z + v1.z) + (v2.z + v3.z)) + ((v4.z + v5.z) + (v6.z + v7.z));
                acc.w += ((v0.w + v1.w) + (v2.w + v3.w)) + ((v4.w + v5.w) + (v6.w + v7.w));
                p += 8 * 32;
            }
            for (; i < len; i++) {
                float4 v = ldcs4(p);
                acc.x += v.x; acc.y += v.y; acc.z += v.z; acc.w += v.w;
                p += 32;
            }

            float* dst = xs + seg * XS_STRIDE + lane * 4;
            const bool excl = (sst[seg] >= a) && (sen[seg] < bnd);
            if (excl) {
                *(float4*)dst = acc;
            } else {
                atomicAdd(dst + 0, acc.x);
                atomicAdd(dst + 1, acc.y);
                atomicAdd(dst + 2, acc.z);
                atomicAdd(dst + 3, acc.w);
            }

            r = e;
            seg++;
        }
    }
    __syncthreads();

    // --- Phase 2: gemm from smem (R7 body, protected) ----------------------
    const int tx = tid & 15;    // n-groups: [tx*4,+4) and [64+tx*4,+4)
    const int ty = tid >> 4;    // m-group: m = ty*2, ty*2+1 (ty 0..35)

    float acc[2][8];
#pragma unroll
    for (int i = 0; i < 2; i++)
#pragma unroll
        for (int j = 0; j < 8; j++) acc[i][j] = 0.f;

    const float* xp0 = xs + (ty * 2 + 0) * XS_STRIDE;
    const float* xp1 = xs + (ty * 2 + 1) * XS_STRIDE;
    const float* wp  = ws + tx * 4;

#pragma unroll 2
    for (int k = 0; k < D; k += 4) {
        float4 xv0 = *(const float4*)(xp0 + k);
        float4 xv1 = *(const float4*)(xp1 + k);
        const float xr[2][4] = {
            {xv0.x, xv0.y, xv0.z, xv0.w},
            {xv1.x, xv1.y, xv1.z, xv1.w},
        };
#pragma unroll
        for (int kk = 0; kk < 4; kk++) {
            float4 w0 = *(const float4*)(wp + (k + kk) * D);
            float4 w1 = *(const float4*)(wp + (k + kk) * D + 64);
#pragma unroll
            for (int i = 0; i < 2; i++) {
                float x = xr[i][kk];
                acc[i][0] += x * w0.x; acc[i][1] += x * w0.y;
                acc[i][2] += x * w0.z; acc[i][3] += x * w0.w;
                acc[i][4] += x * w1.x; acc[i][5] += x * w1.y;
                acc[i][6] += x * w1.z; acc[i][7] += x * w1.w;
            }
        }
    }

    float4 b0 = ((const float4*)b)[tx];
    float4 b1 = ((const float4*)b)[16 + tx];

#pragma unroll
    for (int i = 0; i < 2; i++) {
        int m = ty * 2 + i;
        if (m >= ns) continue;
        float cnt = (float)(sen[m] - sst[m] + 1);

        float4 o0, o1;
        o0.x = acc[i][0] + cnt * b0.x;
        o0.y = acc[i][1] + cnt * b0.y;
        o0.z = acc[i][2] + cnt * b0.z;
        o0.w = acc[i][3] + cnt * b0.w;
        o1.x = acc[i][4] + cnt * b1.x;
        o1.y = acc[i][5] + cnt * b1.y;
        o1.z = acc[i][6] + cnt * b1.z;
        o1.w = acc[i][7] + cnt * b1.w;

        float* op = out + (long long)(m0 + m) * D;
        *(float4*)(op + tx * 4)      = o0;
        *(float4*)(op + 64 + tx * 4) = o1;
    }
}

extern "C" void kernel_launch(void* const* d_in, const int* in_sizes, int n_in,
                              void* d_out, int out_size) {
    const float* input = (const float*)d_in[0];
    const int*   graph = (const int*)  d_in[1];
    const float* W     = (const float*)d_in[2];
    const float* b     = (const float*)d_in[3];
    float*       out   = (float*)d_out;

    cudaFuncSetAttribute(fused_kernel,
                         cudaFuncAttributeMaxDynamicSharedMemorySize, SMEM_T);

    fused_kernel<<<NBLK, BLK, SMEM_T>>>(input, graph, W, b, out);
}